// round 4
// baseline (speedup 1.0000x reference)
#include <cuda_runtime.h>
#include <cstdint>
#include <math.h>

#define T_DIM   1024
#define H_DIM   256
#define NTHREADS 416              // 4 score warps + 1 scan warp + 8 emit warps
#define CHUNK   32                // t-rows per tile
#define NCHUNK  (T_DIM / CHUNK)   // 32
#define PIPE    4                 // smem pipeline stages

#define TILE_FLOATS (CHUNK * H_DIM)   // 8192 floats = 32 KB
#define TILE_BYTES  (TILE_FLOATS * 4)

// smem: buf[PIPE][CHUNK][H] | sS[2][32] | sEv[2][32] | sRv[2][32] | sScale[2] + pad | mbar[PIPE]
#define SMEM_FLOATS (PIPE * TILE_FLOATS + 2 * CHUNK * 3 + 4)
#define SMEM_BYTES  (SMEM_FLOATS * 4 + PIPE * 8)

__device__ __forceinline__ uint32_t smem_u32(const void* p) {
    uint32_t a;
    asm("{ .reg .u64 t; cvta.to.shared.u64 t, %1; cvt.u32.u64 %0, t; }" : "=r"(a) : "l"(p));
    return a;
}
__device__ __forceinline__ void mbar_init(uint32_t mbar, uint32_t count) {
    asm volatile("mbarrier.init.shared.b64 [%0], %1;" :: "r"(mbar), "r"(count) : "memory");
}
__device__ __forceinline__ void mbar_expect_tx(uint32_t mbar, uint32_t bytes) {
    asm volatile("mbarrier.arrive.expect_tx.shared.b64 _, [%0], %1;" :: "r"(mbar), "r"(bytes) : "memory");
}
__device__ __forceinline__ void bulk_g2s(uint32_t dst, const void* src, uint32_t bytes, uint32_t mbar) {
    asm volatile("cp.async.bulk.shared::cta.global.mbarrier::complete_tx::bytes [%0], [%1], %2, [%3];"
                 :: "r"(dst), "l"(src), "r"(bytes), "r"(mbar) : "memory");
}
__device__ __forceinline__ void mbar_wait_parity(uint32_t mbar, uint32_t parity) {
    uint32_t done;
    asm volatile(
        "{\n\t.reg .pred p;\n\t"
        "mbarrier.try_wait.parity.acquire.cta.shared::cta.b64 p, [%1], %2;\n\t"
        "selp.b32 %0, 1, 0, p;\n\t}"
        : "=r"(done) : "r"(mbar), "r"(parity) : "memory");
    if (!done) {
        asm volatile(
            "{\n\t.reg .pred P1;\n\t"
            "WL_%=:\n\t"
            "mbarrier.try_wait.parity.acquire.cta.shared::cta.b64 P1, [%0], %1, 0x989680;\n\t"
            "@P1 bra.uni WD_%=;\n\t"
            "bra.uni WL_%=;\n\t"
            "WD_%=:\n\t}"
            :: "r"(mbar), "r"(parity) : "memory");
    }
}
__device__ __forceinline__ void bar_sync(int id, int count) {
    asm volatile("bar.sync %0, %1;" :: "r"(id), "r"(count) : "memory");
}
__device__ __forceinline__ void bar_arrive(int id, int count) {
    asm volatile("bar.arrive %0, %1;" :: "r"(id), "r"(count) : "memory");
}

// Named barrier ids (count):
//  1+buf (160): sS_ready   score(128 arrive) -> scan(32 sync)
//  3+buf (160): sS_free    scan(32 arrive)  -> score(128 sync)
//  5+buf (288): coef_ready scan(32 arrive)  -> emit(256 sync)
//  7+buf (288): coef_free  emit(256 arrive) -> scan(32 sync)
//  9     (256): emit-internal (tile fully read before refill)

__global__ __launch_bounds__(NTHREADS, 1)
void temporal_attn_causal_kernel(const float* __restrict__ h,
                                 const float* __restrict__ attn_w,
                                 const float* __restrict__ attn_b,
                                 float* __restrict__ out) {
    extern __shared__ __align__(16) unsigned char smem_raw[];
    float*    buf    = (float*)smem_raw;                       // PIPE tiles
    float*    sS     = buf + PIPE * TILE_FLOATS;               // [2][CHUNK]
    float*    sEv    = sS + 2 * CHUNK;                         // [2][CHUNK]
    float*    sRv    = sEv + 2 * CHUNK;                        // [2][CHUNK]
    float*    sScale = sRv + 2 * CHUNK;                        // [2] (+pad)
    uint64_t* mbar   = (uint64_t*)(sScale + 4);

    const int bl   = blockIdx.x;               // one CTA per (b,l): 128
    const int tid  = threadIdx.x;
    const int lane = tid & 31;

    const float* __restrict__ hb = h + (size_t)bl * T_DIM * H_DIM;
    float* __restrict__ ob = out + (size_t)bl * T_DIM * H_DIM;

    if (tid == 0) {
        #pragma unroll
        for (int s = 0; s < PIPE; s++) mbar_init(smem_u32(&mbar[s]), 1);
        asm volatile("fence.proxy.async.shared::cta;" ::: "memory");
    }
    __syncthreads();
    if (tid == 0) {
        #pragma unroll
        for (int s = 0; s < PIPE; s++) {
            uint32_t mb = smem_u32(&mbar[s]);
            mbar_expect_tx(mb, TILE_BYTES);
            bulk_g2s(smem_u32(buf + s * TILE_FLOATS),
                     hb + (size_t)s * TILE_FLOATS, TILE_BYTES, mb);
        }
    }
    __syncthreads();

    if (tid < 128) {
        // ================= SCORE GROUP: warps 0-3, 8 rows each =================
        const int warp = tid >> 5;
        const float4* __restrict__ w4 = (const float4*)attn_w;
        const float4 wv0 = w4[lane];
        const float4 wv1 = w4[lane + 32];
        const float bias = attn_b[0];

        for (int g = 0; g < NCHUNK; g++) {
            const int stage = g & (PIPE - 1);
            const int bsel  = g & 1;
            if (g >= 2) bar_sync(3 + bsel, 160);            // sS[bsel] free
            mbar_wait_parity(smem_u32(&mbar[stage]), (uint32_t)((g / PIPE) & 1));
            const float4* tile4 = (const float4*)(buf + stage * TILE_FLOATS);
            #pragma unroll
            for (int i = 0; i < 8; i++) {
                const int t = warp + i * 4;
                const float4* row = tile4 + t * (H_DIM / 4);
                float4 a = row[lane];
                float4 c = row[lane + 32];
                float d = a.x * wv0.x + a.y * wv0.y + a.z * wv0.z + a.w * wv0.w
                        + c.x * wv1.x + c.y * wv1.y + c.z * wv1.z + c.w * wv1.w;
                d += __shfl_xor_sync(0xffffffffu, d, 16);
                d += __shfl_xor_sync(0xffffffffu, d, 8);
                d += __shfl_xor_sync(0xffffffffu, d, 4);
                d += __shfl_xor_sync(0xffffffffu, d, 2);
                d += __shfl_xor_sync(0xffffffffu, d, 1);
                if (lane == 0) sS[bsel * CHUNK + t] = d + bias;
            }
            bar_arrive(1 + bsel, 160);                      // sS[bsel] ready
        }
    } else if (tid < 160) {
        // ================= SCAN WARP: warp 4 =================
        float m_run = -INFINITY;
        float carry = 0.f;
        for (int g = 0; g < NCHUNK; g++) {
            const int bsel = g & 1;
            bar_sync(1 + bsel, 160);                        // sS ready
            float s_k = sS[bsel * CHUNK + lane];
            bar_arrive(3 + bsel, 160);                      // sS free
            if (g >= 2) bar_sync(7 + bsel, 288);            // coef buf free

            float gm = s_k;
            #pragma unroll
            for (int o = 16; o > 0; o >>= 1)
                gm = fmaxf(gm, __shfl_xor_sync(0xffffffffu, gm, o));
            float scale = 1.0f;
            if (gm > m_run) {
                scale = __expf(m_run - gm);                 // 0 on first chunk
                m_run = gm;
            }
            float e = __expf(s_k - m_run);
            float c = e;
            #pragma unroll
            for (int o = 1; o < 32; o <<= 1) {
                float n = __shfl_up_sync(0xffffffffu, c, o);
                if (lane >= o) c += n;
            }
            carry *= scale;
            float tot = carry + c;
            float r = 1.0f / (tot + 1e-12f * __expf(-m_run));
            sEv[bsel * CHUNK + lane] = e;
            sRv[bsel * CHUNK + lane] = r;
            if (lane == 0) sScale[bsel] = scale;
            carry = __shfl_sync(0xffffffffu, tot, 31);
            bar_arrive(5 + bsel, 288);                      // coef ready
        }
    } else {
        // ================= EMIT GROUP: warps 5-12, thread owns dim j =================
        const int j = tid - 160;
        float acc = 0.f;
        for (int g = 0; g < NCHUNK; g++) {
            const int stage = g & (PIPE - 1);
            const int bsel  = g & 1;
            bar_sync(5 + bsel, 288);                        // coef ready (implies tile arrived)
            acc *= sScale[bsel];
            const float* tile = buf + stage * TILE_FLOATS;
            float* outg = ob + (size_t)g * TILE_FLOATS + j;
            const float* ev = sEv + bsel * CHUNK;
            const float* rv = sRv + bsel * CHUNK;
            #pragma unroll
            for (int k = 0; k < CHUNK; k++) {
                float hv = tile[k * H_DIM + j];
                acc = fmaf(ev[k], hv, acc);
                __stcs(outg + k * H_DIM, fmaf(acc, rv[k], hv));
            }
            bar_sync(9, 256);                               // all emit threads done with tile
            if (tid == 160 && g + PIPE < NCHUNK) {
                uint32_t mb = smem_u32(&mbar[stage]);
                mbar_expect_tx(mb, TILE_BYTES);
                bulk_g2s(smem_u32(buf + stage * TILE_FLOATS),
                         hb + (size_t)(g + PIPE) * TILE_FLOATS, TILE_BYTES, mb);
            }
            bar_arrive(7 + bsel, 288);                      // coef buf free
        }
    }
}

extern "C" void kernel_launch(void* const* d_in, const int* in_sizes, int n_in,
                              void* d_out, int out_size) {
    const float* h      = (const float*)d_in[0]; // [8,16,1024,256] f32
    const float* attn_w = (const float*)d_in[1]; // [256] f32
    const float* attn_b = (const float*)d_in[2]; // [1] f32
    float* out = (float*)d_out;
    (void)in_sizes; (void)n_in; (void)out_size;

    cudaFuncSetAttribute(temporal_attn_causal_kernel,
                         cudaFuncAttributeMaxDynamicSharedMemorySize, SMEM_BYTES);
    temporal_attn_causal_kernel<<<128, NTHREADS, SMEM_BYTES>>>(h, attn_w, attn_b, out);
}